// round 2
// baseline (speedup 1.0000x reference)
#include <cuda_runtime.h>
#include <math.h>

// ---------------- problem constants ----------------
#define H1 128
#define W1 160
#define H2 256
#define W2 320
#define HWS1 (H1*W1)   // 20480
#define HWS2 (H2*W2)   // 81920
#define ND1 48
#define ND2 8
#define C1 32
#define C2 16

// ---------------- scratch (device globals; no allocation allowed) ----------------
__device__ float g_rot[2][2][9];
__device__ float g_trans[2][2][3];
__device__ float g_dmin, g_dstep;

__device__ float g_G[27 * ND1 * HWS1];     // 27 channel-reduced conv planes (reused by stage2: 27*8*81920 fits)
__device__ float g_cost[ND1 * HWS1];       // cost volume (stage2 fits)
__device__ float g_samps[ND1 * HWS1];      // depth samples per voxel-plane (stage2 fits: 8*81920)

// ---------------- setup: compose projections, invert ref, per-view rot/trans ----------------
__device__ void mat4_inv_d(const double* M, double* out) {
    double a[4][8];
    for (int i = 0; i < 4; i++)
        for (int j = 0; j < 4; j++) { a[i][j] = M[i*4+j]; a[i][j+4] = (i==j) ? 1.0 : 0.0; }
    for (int col = 0; col < 4; col++) {
        int piv = col; double best = fabs(a[col][col]);
        for (int r = col+1; r < 4; r++) if (fabs(a[r][col]) > best) { best = fabs(a[r][col]); piv = r; }
        if (piv != col) for (int j = 0; j < 8; j++) { double t = a[col][j]; a[col][j] = a[piv][j]; a[piv][j] = t; }
        double d = a[col][col];
        for (int j = 0; j < 8; j++) a[col][j] /= d;
        for (int r = 0; r < 4; r++) if (r != col) {
            double f = a[r][col];
            for (int j = 0; j < 8; j++) a[r][j] -= f * a[col][j];
        }
    }
    for (int i = 0; i < 4; i++) for (int j = 0; j < 4; j++) out[i*4+j] = a[i][j+4];
}

__global__ void setup_kernel(const float* __restrict__ proj1,
                             const float* __restrict__ proj2,
                             const float* __restrict__ depthv) {
    if (threadIdx.x != 0 || blockIdx.x != 0) return;
    for (int s = 0; s < 2; s++) {
        const float* P = s ? proj2 : proj1;   // (3 views, 2, 4, 4)
        double comp[3][16];
        for (int v = 0; v < 3; v++) {
            const float* E   = P + v*32;
            const float* Kin = P + v*32 + 16;
            for (int i = 0; i < 16; i++) comp[v][i] = (double)E[i];
            for (int i = 0; i < 3; i++)
                for (int j = 0; j < 4; j++) {
                    double t = 0.0;
                    for (int k = 0; k < 3; k++) t += (double)Kin[i*4+k] * (double)E[k*4+j];
                    comp[v][i*4+j] = t;
                }
        }
        double inv[16];
        mat4_inv_d(comp[0], inv);
        for (int v = 1; v < 3; v++) {
            double R[16];
            for (int i = 0; i < 4; i++)
                for (int j = 0; j < 4; j++) {
                    double t = 0.0;
                    for (int k = 0; k < 4; k++) t += comp[v][i*4+k] * inv[k*4+j];
                    R[i*4+j] = t;
                }
            for (int i = 0; i < 3; i++) {
                for (int j = 0; j < 3; j++) g_rot[s][v-1][i*3+j] = (float)R[i*4+j];
                g_trans[s][v-1][i] = (float)R[i*4+3];
            }
        }
    }
    g_dmin  = depthv[0];
    g_dstep = (depthv[ND1-1] - depthv[0]) / (float)(ND1 - 1);
}

// ---------------- depth sample generation ----------------
__global__ void samps1_kernel() {
    int i = blockIdx.x * blockDim.x + threadIdx.x;
    if (i >= ND1 * HWS1) return;
    int d = i / HWS1;
    g_samps[i] = g_dmin + (float)d * g_dstep;
}

__device__ __forceinline__ float resize2x_sample(const float* __restrict__ src, int h, int w) {
    // jax.image.resize bilinear 2x up: src coord = 0.5*i - 0.25, edge-renormalized == clamped
    float fy = 0.5f * (float)h - 0.25f;
    float fx = 0.5f * (float)w - 0.25f;
    float y0f = floorf(fy), x0f = floorf(fx);
    float ty = fy - y0f, tx = fx - x0f;
    int y0 = (int)y0f, x0 = (int)x0f;
    int y0c = min(max(y0, 0), H1-1), y1c = min(max(y0+1, 0), H1-1);
    int x0c = min(max(x0, 0), W1-1), x1c = min(max(x0+1, 0), W1-1);
    float v00 = src[y0c*W1 + x0c], v01 = src[y0c*W1 + x1c];
    float v10 = src[y1c*W1 + x0c], v11 = src[y1c*W1 + x1c];
    return (v00*(1.f-tx) + v01*tx)*(1.f-ty) + (v10*(1.f-tx) + v11*tx)*ty;
}

__global__ void samps2_kernel(const float* __restrict__ d1, const float* __restrict__ v1) {
    int p = blockIdx.x * blockDim.x + threadIdx.x;
    if (p >= HWS2) return;
    int h = p / W2, w = p % W2;
    float cd = resize2x_sample(d1, h, w);
    float cv = resize2x_sample(v1, h, w);
    float low  = -fminf(cd, cv);
    float step = (cv - low) / (float)(ND2 - 1);
    #pragma unroll
    for (int d = 0; d < ND2; d++)
        g_samps[d*HWS2 + p] = cd + low + step*(float)d + 1e-12f;
}

// ---------------- pass1: warp + variance + channel-reduced conv taps ----------------
template<int C, int D, int H, int W>
__global__ void pass1_kernel(const float* __restrict__ feats,   // (3, C, H, W)
                             const float* __restrict__ wconv,   // (C, 27)
                             int stage) {
    __shared__ float sw[C * 27];
    for (int i = threadIdx.x; i < C*27; i += blockDim.x) sw[i] = wconv[i];
    __syncthreads();

    int idx = blockIdx.x * blockDim.x + threadIdx.x;
    if (idx >= D * H * W) return;
    int hw = idx % (H * W);
    int h = hw / W, w = hw % W;

    float depth = g_samps[idx];

    int   off[2][4];
    float wt[2][4];
    #pragma unroll
    for (int v = 0; v < 2; v++) {
        const float* R = g_rot[stage][v];
        const float* T = g_trans[stage][v];
        float fx = (float)w, fy = (float)h;
        float px = (R[0]*fx + R[1]*fy + R[2]) * depth + T[0];
        float py = (R[3]*fx + R[4]*fy + R[5]) * depth + T[1];
        float pz = (R[6]*fx + R[7]*fy + R[8]) * depth + T[2];
        float gx = px / pz / (0.5f*(float)(W-1)) - 1.0f;
        float gy = py / pz / (0.5f*(float)(H-1)) - 1.0f;
        float ix = ((gx + 1.0f)*(float)W - 1.0f) * 0.5f;
        float iy = ((gy + 1.0f)*(float)H - 1.0f) * 0.5f;
        // safe-cast clamp; taps this far out are invalid (weight 0) anyway
        ix = fminf(fmaxf(ix, -8.0f), (float)(W+8));
        iy = fminf(fmaxf(iy, -8.0f), (float)(H+8));
        float x0f = floorf(ix), y0f = floorf(iy);
        float tx = ix - x0f, ty = iy - y0f;
        int x0 = (int)x0f, y0 = (int)y0f;
        bool vx0 = (x0   >= 0) && (x0   <= W-1);
        bool vx1 = (x0+1 >= 0) && (x0+1 <= W-1);
        bool vy0 = (y0   >= 0) && (y0   <= H-1);
        bool vy1 = (y0+1 >= 0) && (y0+1 <= H-1);
        int x0c = min(max(x0,   0), W-1), x1c = min(max(x0+1, 0), W-1);
        int y0c = min(max(y0,   0), H-1), y1c = min(max(y0+1, 0), H-1);
        off[v][0] = y0c*W + x0c;  off[v][1] = y0c*W + x1c;
        off[v][2] = y1c*W + x0c;  off[v][3] = y1c*W + x1c;
        wt[v][0] = (vx0 && vy0) ? (1.f-tx)*(1.f-ty) : 0.f;
        wt[v][1] = (vx1 && vy0) ? tx*(1.f-ty)       : 0.f;
        wt[v][2] = (vx0 && vy1) ? (1.f-tx)*ty       : 0.f;
        wt[v][3] = (vx1 && vy1) ? tx*ty             : 0.f;
    }

    const float* f0 = feats + hw;          // ref view, channel-strided
    const float* f1 = feats + 1*C*H*W;
    const float* f2 = feats + 2*C*H*W;

    float acc[27];
    #pragma unroll
    for (int k = 0; k < 27; k++) acc[k] = 0.f;

    #pragma unroll 4
    for (int c = 0; c < C; c++) {
        float r = f0[c*H*W];
        const float* b1p = f1 + c*H*W;
        const float* b2p = f2 + c*H*W;
        float v1 = wt[0][0]*b1p[off[0][0]] + wt[0][1]*b1p[off[0][1]]
                 + wt[0][2]*b1p[off[0][2]] + wt[0][3]*b1p[off[0][3]];
        float v2 = wt[1][0]*b2p[off[1][0]] + wt[1][1]*b2p[off[1][1]]
                 + wt[1][2]*b2p[off[1][2]] + wt[1][3]*b2p[off[1][3]];
        float s = r + v1 + v2;
        float q = r*r + v1*v1 + v2*v2;
        float m = s * (1.0f/3.0f);
        float var = q * (1.0f/3.0f) - m*m;
        #pragma unroll
        for (int k = 0; k < 27; k++)
            acc[k] = fmaf(var, sw[c*27 + k], acc[k]);
    }

    #pragma unroll
    for (int k = 0; k < 27; k++)
        g_G[k*(D*H*W) + idx] = acc[k];
}

// ---------------- pass2: 27-tap gather (zero-pad SAME) -> cost volume ----------------
template<int D, int H, int W>
__global__ void cost_kernel(const float* __restrict__ bias) {
    int idx = blockIdx.x * blockDim.x + threadIdx.x;
    if (idx >= D * H * W) return;
    int hw = idx % (H * W);
    int d = idx / (H * W);
    int h = hw / W, w = hw % W;
    float s = bias[0];
    #pragma unroll
    for (int kd = 0; kd < 3; kd++) {
        int dd = d + kd - 1;
        if (dd < 0 || dd >= D) continue;
        #pragma unroll
        for (int kh = 0; kh < 3; kh++) {
            int hh = h + kh - 1;
            if (hh < 0 || hh >= H) continue;
            #pragma unroll
            for (int kw = 0; kw < 3; kw++) {
                int ww = w + kw - 1;
                if (ww < 0 || ww >= W) continue;
                s += g_G[(kd*9 + kh*3 + kw)*(D*H*W) + dd*(H*W) + hh*W + ww];
            }
        }
    }
    g_cost[idx] = s;
}

// ---------------- per-pixel: softmax, depth, conf, exp_var ----------------
template<int D, int H, int W>
__global__ void pixel_kernel(float* __restrict__ outd,
                             float* __restrict__ outc,
                             float* __restrict__ outv) {
    int p = blockIdx.x * blockDim.x + threadIdx.x;
    if (p >= H * W) return;

    float e[D], sp[D];
    float m = -1e30f;
    #pragma unroll
    for (int d = 0; d < D; d++) { e[d] = g_cost[d*(H*W) + p]; m = fmaxf(m, e[d]); }
    float sum = 0.f;
    #pragma unroll
    for (int d = 0; d < D; d++) { e[d] = expf(e[d] - m); sum += e[d]; }
    float inv = 1.0f / sum;
    float depth = 0.f, dif = 0.f;
    #pragma unroll
    for (int d = 0; d < D; d++) {
        float pr = e[d] * inv;
        e[d] = pr;
        float s = g_samps[d*(H*W) + p];
        sp[d] = s;
        depth += pr * s;
        dif   += pr * (float)d;
    }
    float var = 0.f;
    #pragma unroll
    for (int d = 0; d < D; d++) {
        float t = sp[d] - depth;
        var += t * t * e[d];
    }
    int di = min(max((int)dif, 0), D-1);
    float conf = 0.f;
    #pragma unroll
    for (int d = 0; d < D; d++)
        if (d >= di-1 && d <= di+2) conf += e[d];

    outd[p] = depth;
    outc[p] = conf;
    outv[p] = 1.5f * sqrtf(var);
}

// ---------------- launch ----------------
extern "C" void kernel_launch(void* const* d_in, const int* in_sizes, int n_in,
                              void* d_out, int out_size) {
    const float* feats1 = (const float*)d_in[0];
    const float* feats2 = (const float*)d_in[1];
    const float* proj1  = (const float*)d_in[2];
    const float* proj2  = (const float*)d_in[3];
    const float* depthv = (const float*)d_in[4];
    const float* w1     = (const float*)d_in[6];
    const float* b1     = (const float*)d_in[7];
    const float* w2     = (const float*)d_in[8];
    const float* b2     = (const float*)d_in[9];

    float* out = (float*)d_out;
    float* o_d1 = out;
    float* o_c1 = out + HWS1;
    float* o_v1 = out + 2*HWS1;
    float* o_d2 = out + 3*HWS1;
    float* o_c2 = out + 3*HWS1 + HWS2;
    float* o_v2 = out + 3*HWS1 + 2*HWS2;

    setup_kernel<<<1, 1>>>(proj1, proj2, depthv);

    // ---- stage 1 ----
    {
        int nvox = ND1 * HWS1;
        samps1_kernel<<<(nvox + 255)/256, 256>>>();
        pass1_kernel<C1, ND1, H1, W1><<<(nvox + 255)/256, 256>>>(feats1, w1, 0);
        cost_kernel<ND1, H1, W1><<<(nvox + 255)/256, 256>>>(b1);
        pixel_kernel<ND1, H1, W1><<<(HWS1 + 255)/256, 256>>>(o_d1, o_c1, o_v1);
    }

    // ---- stage 2 ----
    {
        int nvox = ND2 * HWS2;
        samps2_kernel<<<(HWS2 + 255)/256, 256>>>(o_d1, o_v1);
        pass1_kernel<C2, ND2, H2, W2><<<(nvox + 255)/256, 256>>>(feats2, w2, 1);
        cost_kernel<ND2, H2, W2><<<(nvox + 255)/256, 256>>>(b2);
        pixel_kernel<ND2, H2, W2><<<(HWS2 + 255)/256, 256>>>(o_d2, o_c2, o_v2);
    }
}